// round 14
// baseline (speedup 1.0000x reference)
#include <cuda_runtime.h>
#include <math.h>

#define T_SNAP 4
#define EQ     4096
#define NNODES 8192
#define H      32
#define BCAP   32                // in-edge bucket capacity per (t, node)
#define RCAP   128               // per-query reach-set capacity
#define HT     16384             // global hash table slots (power of 2)
#define NQ     (T_SNAP * EQ)     // 16384 queries
#define NB     (EQ * 3)          // pooled nodes (GRU batch)

// Scratch (static device globals, zero-initialized; every call restores zeros)
__device__ int    g_bcnt[T_SNAP * NNODES];
__device__ int    g_bsrc[T_SNAP * NNODES * BCAP];
__device__ float  g_tops[NQ * 3];
__device__ int    g_htkey[HT];             // 0 = empty (reset by GRU consumers)
__device__ float4 g_slotv[HT];
__device__ float  g_uh[HT * H];
__device__ int    g_bslot[NB];
__device__ int    g_uniq[NB];
__device__ int    g_uniq_cnt;              // reset by k_gather

__device__ __forceinline__ float fast_sigmoid(float x) {
    return 1.f / (1.f + __expf(-x));
}
__device__ __forceinline__ float fast_tanh(float x) {
    return 2.f / (1.f + __expf(-2.f * x)) - 1.f;
}

__device__ __forceinline__ bool in_list(const int* l, int n, int x) {
    for (int i = 0; i < n; i++)
        if (l[i] == x) return true;
    return false;
}

// 2-hop backward BFS from seed within snapshot t; returns set size
__device__ __forceinline__ int bfs2(int t, int seed, int* R) {
    R[0] = seed;
    int n = 1, s = 0, e = 1;
#pragma unroll
    for (int hop = 0; hop < 2; hop++) {
        for (int i = s; i < e; i++) {
            int node = R[i];
            int c = __ldg(&g_bcnt[t * NNODES + node]);
            if (c > BCAP) c = BCAP;
            const int* b = &g_bsrc[(t * NNODES + node) * BCAP];
            for (int j = 0; j < c; j++) {
                int src = __ldg(&b[j]);
                if (!in_list(R, n, src) && n < RCAP) R[n++] = src;
            }
        }
        s = e; e = n;
    }
    return n;
}

// ---------------------------------------------------------------------------
// K0: scatter (t, e) -> bucket of srcs at dst
__global__ void __launch_bounds__(256)
k_scat(const int* __restrict__ ei) {
    int idx = blockIdx.x * 256 + threadIdx.x;
    if (idx >= NQ) return;
    int t = idx >> 12;                 // EQ = 4096
    int e = idx & (EQ - 1);
    int src = __ldg(&ei[t * 2 * EQ + e]);
    int dst = __ldg(&ei[t * 2 * EQ + EQ + e]);
    int pos = atomicAdd(&g_bcnt[t * NNODES + dst], 1);
    if (pos < BCAP) g_bsrc[(t * NNODES + dst) * BCAP + pos] = src;
}

// ---------------------------------------------------------------------------
// K1: thread-per-(t,q) query + top-3 (R6 body, no barrier; every 4th lane)
__global__ void __launch_bounds__(256, 2)
k_query(const int* __restrict__ ei) {
    int idx = blockIdx.x * 256 + threadIdx.x;
    if ((idx & 3) != 0) return;
    int qi = idx >> 2;
    if (qi >= NQ) return;
    int t = qi >> 12;
    int q = qi & (EQ - 1);
    int u = __ldg(&ei[(T_SNAP - 1) * 2 * EQ + q]);
    int v = __ldg(&ei[(T_SNAP - 1) * 2 * EQ + EQ + q]);

    int Ru[RCAP], Rv[RCAP];
    int nu = bfs2(t, u, Ru);
    int nv = bfs2(t, v, Rv);

    float t0 = 0.f, t1 = 0.f, t2 = 0.f;
    for (int pass = 0; pass < 2; pass++) {
        const int* L = pass ? Rv : Ru;
        int nL = pass ? nv : nu;
        for (int i = 0; i < nL; i++) {
            int node = L[i];
            bool inRu, inRv;
            if (pass == 0) {
                inRu = true;
                inRv = in_list(Rv, nv, node);
            } else {
                inRu = in_list(Ru, nu, node);
                if (inRu) continue;        // handled in pass 0
                inRv = true;
            }
            int c = __ldg(&g_bcnt[t * NNODES + node]);
            if (c > BCAP) c = BCAP;
            const int* b = &g_bsrc[(t * NNODES + node) * BCAP];
            int d = 0;
            for (int j = 0; j < c; j++) {
                int src = __ldg(&b[j]);
                bool su = inRu && in_list(Ru, nu, src);
                bool sv = inRv && in_list(Rv, nv, src);
                if (su || sv) d++;
            }
            float f = (float)d;
            if (f > t0)      { t2 = t1; t1 = t0; t0 = f; }
            else if (f > t1) { t2 = t1; t1 = f; }
            else if (f > t2) { t2 = f; }
        }
    }
    g_tops[qi * 3 + 0] = t0;
    g_tops[qi * 3 + 1] = t1;
    g_tops[qi * 3 + 2] = t2;
}

// ---------------------------------------------------------------------------
// K2: hierarchical dedup (block SMEM hash -> global, reps only) + bcnt clear
__global__ void __launch_bounds__(256)
k_dedup() {
    __shared__ int skey[512];      // block-level table: 0 = empty (<=256 keys)
    __shared__ int sslot[512];

    int tid = threadIdx.x;
    int idx = blockIdx.x * 256 + tid;    // == b (48*256 == NB)

    // clear bucket counters for next call (k_query already consumed them)
    for (int i = idx; i < T_SNAP * NNODES; i += NB) g_bcnt[i] = 0;

    for (int i = tid; i < 512; i += 256) skey[i] = 0;
    __syncthreads();

    int b = idx;
    int q = b / 3, p = b - q * 3;
    float v0 = g_tops[(0 * EQ + q) * 3 + p];
    float v1 = g_tops[(1 * EQ + q) * 3 + p];
    float v2 = g_tops[(2 * EQ + q) * 3 + p];
    float v3 = g_tops[(3 * EQ + q) * 3 + p];
    // degrees <= BCAP = 32: always packable; tag bit keeps key nonzero
    int key = (int)v0 | ((int)v1 << 8) | ((int)v2 << 16) | ((int)v3 << 24)
            | 0x40000000;

    // block-level insert (smem CAS, cheap)
    unsigned hb = ((unsigned)key * 2654435761u >> 14) & 511u;
    int bi;
    bool rep = false;
    for (;;) {
        int old = atomicCAS(&skey[hb], 0, key);
        if (old == 0)  { rep = true; bi = (int)hb; break; }
        if (old == key) { bi = (int)hb; break; }
        hb = (hb + 1) & 511u;
    }

    // block reps resolve globally (<= 48 contenders per hot key)
    if (rep) {
        unsigned hg = ((unsigned)key * 2654435761u) & (HT - 1);
        int slot;
        for (;;) {
            int cur = ((volatile int*)g_htkey)[hg];
            if (cur == key) { slot = (int)hg; break; }
            if (cur == 0) {
                int old = atomicCAS(&g_htkey[hg], 0, key);
                if (old == 0) {
                    g_slotv[hg] = make_float4(v0, v1, v2, v3);
                    int u = atomicAdd(&g_uniq_cnt, 1);
                    g_uniq[u] = (int)hg;
                    slot = (int)hg;
                    break;
                }
                if (old == key) { slot = (int)hg; break; }
            }
            hg = (hg + 1) & (HT - 1);
        }
        sslot[bi] = slot;
    }
    __syncthreads();
    g_bslot[b] = sslot[bi];
}

// ---------------------------------------------------------------------------
// K3: warp-per-unique GRU; gi(v<=32) table in SMEM; resets consumed slots
__global__ void __launch_bounds__(128)
k_gru(const float* __restrict__ Wg,  const float* __restrict__ bg,
      const float* __restrict__ Wih, const float* __restrict__ Whh,
      const float* __restrict__ bih, const float* __restrict__ bhh) {
    __shared__ float sWih[3 * H * H];      // [j*H + kk] (for gi build)
    __shared__ float sWhhT[H][3 * H];      // [kk][j], conflict-free
    __shared__ float sgi[33][3 * H];       // gi(v), degrees 0..32
    __shared__ float sbhh[3 * H];
    __shared__ float sWg[H], sbg[H];

    int tid = threadIdx.x;
    for (int i = tid; i < 3 * H * H; i += 128) {
        sWih[i] = Wih[i];
        int j = i / H, kk = i - j * H;
        sWhhT[kk][j] = Whh[i];
    }
    if (tid < 3 * H) sbhh[tid] = bhh[tid];
    if (tid < H) { sWg[tid] = Wg[tid]; sbg[tid] = bg[tid]; }
    __syncthreads();

    // gi[v][j] = bih[j] + sum_k Wih[j,k] * relu(v*Wg[k] + bg[k])
    for (int i = tid; i < 33 * 3 * H; i += 128) {
        int v = i / (3 * H);
        int j = i - v * (3 * H);
        float acc = __ldg(&bih[j]);
        float fv = (float)v;
#pragma unroll
        for (int kk = 0; kk < H; kk++) {
            float xk = fmaxf(fv * sWg[kk] + sbg[kk], 0.f);
            acc += sWih[j * H + kk] * xk;
        }
        sgi[v][j] = acc;
    }
    __syncthreads();

    int cnt = g_uniq_cnt;
    int lane = tid & 31;
    int w = blockIdx.x * 4 + (tid >> 5);       // 96 blocks x 4 warps = 384
    for (int u = w; u < cnt; u += 96 * 4) {
        int slot = g_uniq[u];
        float4 vv = g_slotv[slot];
        float vs[4] = {vv.x, vv.y, vv.z, vv.w};

        float pr[4], pz[4], pg[4];
#pragma unroll
        for (int t = 0; t < T_SNAP; t++) {
            const float* gp = sgi[(int)vs[t]];     // degree <= 32 always
            pr[t] = gp[lane];
            pz[t] = gp[H + lane];
            pg[t] = gp[2 * H + lane];
        }

        float h = 0.f;
#pragma unroll
        for (int t = 0; t < T_SNAP; t++) {
            float hr = sbhh[lane], hz = sbhh[H + lane], hg = sbhh[2 * H + lane];
#pragma unroll
            for (int kk = 0; kk < H; kk++) {
                float hk = __shfl_sync(0xffffffffu, h, kk);
                hr += sWhhT[kk][lane]         * hk;
                hz += sWhhT[kk][H + lane]     * hk;
                hg += sWhhT[kk][2 * H + lane] * hk;
            }
            float r = fast_sigmoid(pr[t] + hr);
            float z = fast_sigmoid(pz[t] + hz);
            float n = fast_tanh(pg[t] + r * hg);
            h = (1.f - z) * n + z * h;
        }
        g_uh[slot * H + lane] = h;
        if (lane == 0) g_htkey[slot] = 0;   // reset consumed slot for next call
    }
}

// ---------------------------------------------------------------------------
// K4: parallel coalesced gather to output + uniq counter reset
__global__ void __launch_bounds__(256)
k_gather(float* __restrict__ out) {
    int i = blockIdx.x * 256 + threadIdx.x;
    if (i == 0) g_uniq_cnt = 0;            // reset for next call
    if (i >= NB * H) return;
    int b = i >> 5;
    int j = i & (H - 1);
    out[i] = g_uh[g_bslot[b] * H + j];
}

// ---------------------------------------------------------------------------
extern "C" void kernel_launch(void* const* d_in, const int* in_sizes, int n_in,
                              void* d_out, int out_size) {
    const int*   ei  = (const int*)d_in[0];
    const float* Wg  = (const float*)d_in[1];
    const float* bg  = (const float*)d_in[2];
    const float* Wih = (const float*)d_in[3];
    const float* Whh = (const float*)d_in[4];
    const float* bih = (const float*)d_in[5];
    const float* bhh = (const float*)d_in[6];
    float* out = (float*)d_out;

    k_scat  <<<NQ / 256, 256>>>(ei);                     // 64 blocks
    k_query <<<296, 256>>>(ei);                          // no barrier inside
    k_dedup <<<NB / 256, 256>>>();                       // 48 blocks
    k_gru   <<<96, 128>>>(Wg, bg, Wih, Whh, bih, bhh);   // 384 warps
    k_gather<<<(NB * H) / 256, 256>>>(out);              // 1536 blocks
}